// round 2
// baseline (speedup 1.0000x reference)
#include <cuda_runtime.h>

// MK-MMD, linear-time estimator:
//   loss = (1/B) * sum_i sum_alpha [ K(|zs_i - zs_j|^2) + K(|zt_i - zt_j|^2)
//                                  - K(|zs_i - zt_j|^2) - K(|zs_j - zt_i|^2) ],  j = (i+1) % B
//   K(d) = exp(-d / (2 * alpha * mean_d2))
//   mean_d2 = (2*N*sum(f^2) - 2*||colsum(f)||^2) / N^2,  f = [zs; zt], N = 2B
// (clamp max(d2,0) in the reference only touches the ~0 diagonal: negligible)

static const int BN = 2048;        // B
static const int D4 = 256;         // D / 4 (float4 per row)
static const int ROWBLKS = 64;     // column-sum row blocks over the 4096 rows
static const int ROWS_PER_BLK = 64;

__device__ float  g_dist[4 * BN];               // [i][{ss,tt,st,ts}]
__device__ float4 g_colsum_part[ROWBLKS * D4];  // per-rowblock partial column sums
__device__ float  g_sumsq_part[ROWBLKS];        // per-rowblock partial sum of squares

__device__ __forceinline__ float sq4(float4 a, float4 b) {
    float x = a.x - b.x, y = a.y - b.y, z = a.z - b.z, w = a.w - b.w;
    return x * x + y * y + z * z + w * w;
}

__global__ __launch_bounds__(256)
void mk_main_pass(const float4* __restrict__ zs, const float4* __restrict__ zt) {
    const int t = threadIdx.x;
    const int bid = blockIdx.x;

    if (bid < BN) {
        // ---- distance block: 4 pairwise sq-distances for index i ----
        const int i = bid;
        const int j = (bid + 1) & (BN - 1);
        float4 a = zs[i * D4 + t];
        float4 b = zs[j * D4 + t];
        float4 c = zt[i * D4 + t];
        float4 e = zt[j * D4 + t];
        float v0 = sq4(a, b);   // |zs_i - zs_j|^2
        float v1 = sq4(c, e);   // |zt_i - zt_j|^2
        float v2 = sq4(a, e);   // |zs_i - zt_j|^2
        float v3 = sq4(b, c);   // |zs_j - zt_i|^2
        #pragma unroll
        for (int o = 16; o > 0; o >>= 1) {
            v0 += __shfl_down_sync(0xffffffffu, v0, o);
            v1 += __shfl_down_sync(0xffffffffu, v1, o);
            v2 += __shfl_down_sync(0xffffffffu, v2, o);
            v3 += __shfl_down_sync(0xffffffffu, v3, o);
        }
        __shared__ float s[8][4];
        if ((t & 31) == 0) {
            int w = t >> 5;
            s[w][0] = v0; s[w][1] = v1; s[w][2] = v2; s[w][3] = v3;
        }
        __syncthreads();
        if (t < 4) {
            float sum = 0.f;
            #pragma unroll
            for (int w = 0; w < 8; w++) sum += s[w][t];
            g_dist[i * 4 + t] = sum;
        }
    } else {
        // ---- column-sum / sum-of-squares block ----
        const int rb = bid - BN;
        const float4* src;
        int base;
        if (rb < ROWBLKS / 2) { src = zs; base = rb * ROWS_PER_BLK; }
        else                  { src = zt; base = (rb - ROWBLKS / 2) * ROWS_PER_BLK; }

        float4 acc = make_float4(0.f, 0.f, 0.f, 0.f);
        float ss = 0.f;
        #pragma unroll 4
        for (int r = 0; r < ROWS_PER_BLK; r++) {
            float4 v = src[(base + r) * D4 + t];
            acc.x += v.x; acc.y += v.y; acc.z += v.z; acc.w += v.w;
            ss += v.x * v.x + v.y * v.y + v.z * v.z + v.w * v.w;
        }
        g_colsum_part[rb * D4 + t] = acc;

        #pragma unroll
        for (int o = 16; o > 0; o >>= 1) ss += __shfl_down_sync(0xffffffffu, ss, o);
        __shared__ float sw[8];
        if ((t & 31) == 0) sw[t >> 5] = ss;
        __syncthreads();
        if (t == 0) {
            float sum = 0.f;
            #pragma unroll
            for (int w = 0; w < 8; w++) sum += sw[w];
            g_sumsq_part[rb] = sum;
        }
    }
}

__global__ __launch_bounds__(1024)
void mk_finalize(float* __restrict__ out) {
    const int t = threadIdx.x;
    __shared__ float red[1024];
    __shared__ float coef[3];

    // reduce colsum partials -> ||colsum||^2 contribution
    float local_sq = 0.f;
    if (t < D4) {
        float4 s = make_float4(0.f, 0.f, 0.f, 0.f);
        #pragma unroll 4
        for (int p = 0; p < ROWBLKS; p++) {
            float4 v = g_colsum_part[p * D4 + t];
            s.x += v.x; s.y += v.y; s.z += v.z; s.w += v.w;
        }
        local_sq = s.x * s.x + s.y * s.y + s.z * s.z + s.w * s.w;
    }
    float local_ss = (t < ROWBLKS) ? g_sumsq_part[t] : 0.f;

    red[t] = local_sq;
    __syncthreads();
    for (int s = 512; s > 0; s >>= 1) { if (t < s) red[t] += red[t + s]; __syncthreads(); }
    float S2 = red[0];
    __syncthreads();

    red[t] = local_ss;
    __syncthreads();
    for (int s = 512; s > 0; s >>= 1) { if (t < s) red[t] += red[t + s]; __syncthreads(); }
    float SS = red[0];
    __syncthreads();

    if (t == 0) {
        const double N = 2.0 * (double)BN;
        double mean_d2 = (2.0 * N * (double)SS - 2.0 * (double)S2) / (N * N);
        const double alphas[3] = {0.5, 1.0, 2.0};
        #pragma unroll
        for (int a = 0; a < 3; a++)
            coef[a] = (float)(-1.0 / (2.0 * alphas[a] * mean_d2));
    }
    __syncthreads();

    // kernel evaluations + signed sum
    float local = 0.f;
    for (int i = t; i < BN; i += 1024) {
        float dss = g_dist[4 * i + 0];
        float dtt = g_dist[4 * i + 1];
        float dst = g_dist[4 * i + 2];
        float dts = g_dist[4 * i + 3];
        #pragma unroll
        for (int a = 0; a < 3; a++) {
            float c = coef[a];
            local += expf(c * dss) + expf(c * dtt) - expf(c * dst) - expf(c * dts);
        }
    }
    red[t] = local;
    __syncthreads();
    for (int s = 512; s > 0; s >>= 1) { if (t < s) red[t] += red[t + s]; __syncthreads(); }
    if (t == 0) out[0] = red[0] / (float)BN;
}

extern "C" void kernel_launch(void* const* d_in, const int* in_sizes, int n_in,
                              void* d_out, int out_size) {
    const float4* zs = (const float4*)d_in[0];
    const float4* zt = (const float4*)d_in[1];
    mk_main_pass<<<BN + ROWBLKS, 256>>>(zs, zt);
    mk_finalize<<<1, 1024>>>((float*)d_out);
}

// round 3
// speedup vs baseline: 1.5117x; 1.5117x over previous
#include <cuda_runtime.h>

// MK-MMD, linear-time estimator:
//   loss = (1/B) * sum_i sum_alpha [ K(|zs_i-zs_j|^2) + K(|zt_i-zt_j|^2)
//                                  - K(|zs_i-zt_j|^2) - K(|zs_j-zt_i|^2) ], j=(i+1)%B
//   K(d) = exp(-d / (2*alpha*mean_d2))
//   mean_d2 = (2*N*sum(f^2) - 2*||colsum(f)||^2)/N^2, f=[zs;zt], N=2B
// (reference's max(d2,0) clamp only touches the ~0 diagonal: negligible)

static const int BN = 2048;        // B
static const int D4 = 256;         // D/4 (float4 per row)
static const int ROWBLKS = 64;     // colsum row-blocks over 4096 rows
static const int ROWS_PER_BLK = 64;

__device__ float4 g_dist4[BN];                  // {ss, tt, st, ts} per i
__device__ float4 g_colsum_part[ROWBLKS * D4];  // per-rowblock partial column sums
__device__ float  g_sumsq_part[ROWBLKS];        // per-rowblock partial sum of squares

__device__ __forceinline__ float sq4(float4 a, float4 b) {
    float x = a.x - b.x, y = a.y - b.y, z = a.z - b.z, w = a.w - b.w;
    return x * x + y * y + z * z + w * w;
}

__global__ __launch_bounds__(256)
void mk_main_pass(const float4* __restrict__ zs, const float4* __restrict__ zt) {
    const int t = threadIdx.x;
    const int bid = blockIdx.x;

    if (bid < ROWBLKS) {
        // ---- column-sum / sum-of-squares blocks (launched FIRST: they are the
        // long-running ones; starting them in wave 1 overlaps them with the
        // 2048 short distance blocks instead of leaving a tail) ----
        const int rb = bid;
        const float4* src;
        int base;
        if (rb < ROWBLKS / 2) { src = zs; base = rb * ROWS_PER_BLK; }
        else                  { src = zt; base = (rb - ROWBLKS / 2) * ROWS_PER_BLK; }

        float4 acc = make_float4(0.f, 0.f, 0.f, 0.f);
        float ss = 0.f;
        #pragma unroll 4
        for (int r = 0; r < ROWS_PER_BLK; r++) {
            float4 v = src[(base + r) * D4 + t];
            acc.x += v.x; acc.y += v.y; acc.z += v.z; acc.w += v.w;
            ss += v.x * v.x + v.y * v.y + v.z * v.z + v.w * v.w;
        }
        g_colsum_part[rb * D4 + t] = acc;

        #pragma unroll
        for (int o = 16; o > 0; o >>= 1) ss += __shfl_down_sync(0xffffffffu, ss, o);
        __shared__ float sw[8];
        if ((t & 31) == 0) sw[t >> 5] = ss;
        __syncthreads();
        if (t == 0) {
            float sum = 0.f;
            #pragma unroll
            for (int w = 0; w < 8; w++) sum += sw[w];
            g_sumsq_part[rb] = sum;
        }
    } else {
        // ---- distance block: 4 pairwise sq-distances for index i ----
        const int i = bid - ROWBLKS;
        const int j = (i + 1) & (BN - 1);
        float4 a = zs[i * D4 + t];
        float4 b = zs[j * D4 + t];
        float4 c = zt[i * D4 + t];
        float4 e = zt[j * D4 + t];
        float v0 = sq4(a, b);   // |zs_i - zs_j|^2
        float v1 = sq4(c, e);   // |zt_i - zt_j|^2
        float v2 = sq4(a, e);   // |zs_i - zt_j|^2
        float v3 = sq4(b, c);   // |zs_j - zt_i|^2
        #pragma unroll
        for (int o = 16; o > 0; o >>= 1) {
            v0 += __shfl_down_sync(0xffffffffu, v0, o);
            v1 += __shfl_down_sync(0xffffffffu, v1, o);
            v2 += __shfl_down_sync(0xffffffffu, v2, o);
            v3 += __shfl_down_sync(0xffffffffu, v3, o);
        }
        __shared__ float s[8][4];
        if ((t & 31) == 0) {
            int w = t >> 5;
            s[w][0] = v0; s[w][1] = v1; s[w][2] = v2; s[w][3] = v3;
        }
        __syncthreads();
        if (t < 4) {
            float sum = 0.f;
            #pragma unroll
            for (int w = 0; w < 8; w++) sum += s[w][t];
            ((float*)g_dist4)[i * 4 + t] = sum;
        }
    }
}

// Warp-shuffle block reduction for 1024 threads (2 barriers, no tree loop).
__device__ __forceinline__ float block_reduce_1024(float v, float* red) {
    #pragma unroll
    for (int o = 16; o > 0; o >>= 1) v += __shfl_down_sync(0xffffffffu, v, o);
    if ((threadIdx.x & 31) == 0) red[threadIdx.x >> 5] = v;
    __syncthreads();
    if (threadIdx.x < 32) {
        v = red[threadIdx.x];
        #pragma unroll
        for (int o = 16; o > 0; o >>= 1) v += __shfl_down_sync(0xffffffffu, v, o);
        if (threadIdx.x == 0) red[0] = v;
    }
    __syncthreads();
    v = red[0];
    __syncthreads();   // protect red[] for the next reduction
    return v;
}

__global__ __launch_bounds__(1024)
void mk_finalize(float* __restrict__ out) {
    const int t = threadIdx.x;
    __shared__ float4 sm4[3 * D4];   // chunks 1..3 partial colsums (12 KB)
    __shared__ float red[32];
    __shared__ float coef[3];

    // ---- colsum partial reduce: all 1024 threads (4 chunks x 256 cols) ----
    const int col = t & (D4 - 1);
    const int chunk = t >> 8;                // 0..3, 16 partials each
    float4 s = make_float4(0.f, 0.f, 0.f, 0.f);
    #pragma unroll
    for (int p = 0; p < ROWBLKS / 4; p++) {
        float4 v = g_colsum_part[(chunk * (ROWBLKS / 4) + p) * D4 + col];
        s.x += v.x; s.y += v.y; s.z += v.z; s.w += v.w;
    }
    if (chunk > 0) sm4[(chunk - 1) * D4 + col] = s;
    __syncthreads();

    float my_sq = 0.f;
    if (chunk == 0) {
        #pragma unroll
        for (int c = 0; c < 3; c++) {
            float4 v = sm4[c * D4 + col];
            s.x += v.x; s.y += v.y; s.z += v.z; s.w += v.w;
        }
        my_sq = s.x * s.x + s.y * s.y + s.z * s.z + s.w * s.w;
    }
    float my_ss = (t < ROWBLKS) ? g_sumsq_part[t] : 0.f;

    float S2 = block_reduce_1024(my_sq, red);
    float SS = block_reduce_1024(my_ss, red);

    if (t == 0) {
        const double N = 2.0 * (double)BN;
        double mean_d2 = (2.0 * N * (double)SS - 2.0 * (double)S2) / (N * N);
        const double alphas[3] = {0.5, 1.0, 2.0};
        #pragma unroll
        for (int a = 0; a < 3; a++)
            coef[a] = (float)(-1.0 / (2.0 * alphas[a] * mean_d2));
    }
    __syncthreads();

    // ---- kernel evaluations + signed sum (fast exp) ----
    float local = 0.f;
    #pragma unroll
    for (int k = 0; k < BN / 1024; k++) {
        float4 d = g_dist4[k * 1024 + t];
        #pragma unroll
        for (int a = 0; a < 3; a++) {
            float c = coef[a];
            local += __expf(c * d.x) + __expf(c * d.y)
                   - __expf(c * d.z) - __expf(c * d.w);
        }
    }
    float tot = block_reduce_1024(local, red);
    if (t == 0) out[0] = tot / (float)BN;
}

extern "C" void kernel_launch(void* const* d_in, const int* in_sizes, int n_in,
                              void* d_out, int out_size) {
    const float4* zs = (const float4*)d_in[0];
    const float4* zt = (const float4*)d_in[1];
    mk_main_pass<<<BN + ROWBLKS, 256>>>(zs, zt);
    mk_finalize<<<1, 1024>>>((float*)d_out);
}

// round 4
// speedup vs baseline: 1.5312x; 1.0129x over previous
#include <cuda_runtime.h>

// MK-MMD, linear-time estimator:
//   loss = (1/B) * sum_i sum_alpha [ K(|zs_i-zs_j|^2) + K(|zt_i-zt_j|^2)
//                                  - K(|zs_i-zt_j|^2) - K(|zs_j-zt_i|^2) ], j=(i+1)%B
//   K(d) = exp(-d / (2*alpha*mean_d2))
//   mean_d2 = (2*N*sum(f^2) - 2*||colsum(f)||^2)/N^2, f=[zs;zt], N=2B
// (reference's max(d2,0) clamp only touches the ~0 diagonal: negligible)

static const int BN = 2048;        // B
static const int D4 = 256;         // D/4 (float4 per row)
static const int ROWBLKS = 64;     // colsum row-blocks over 4096 rows
static const int ROWS_PER_BLK = 64;

__device__ float4 g_dist4[BN];                  // {ss, tt, st, ts} per i
__device__ float4 g_colsum_part[ROWBLKS * D4];  // per-rowblock partial column sums
__device__ float  g_sumsq_part[ROWBLKS];        // per-rowblock partial sum of squares

__device__ __forceinline__ float sq4(float4 a, float4 b) {
    float x = a.x - b.x, y = a.y - b.y, z = a.z - b.z, w = a.w - b.w;
    return x * x + y * y + z * z + w * w;
}

__global__ __launch_bounds__(256)
void mk_main_pass(const float4* __restrict__ zs, const float4* __restrict__ zt) {
    const int t = threadIdx.x;
    const int bid = blockIdx.x;

    if (bid < ROWBLKS) {
        // ---- column-sum / sum-of-squares blocks (launched FIRST: they are the
        // long-running ones; starting them in wave 1 overlaps them with the
        // 2048 short distance blocks instead of leaving a tail) ----
        const int rb = bid;
        const float4* src;
        int base;
        if (rb < ROWBLKS / 2) { src = zs; base = rb * ROWS_PER_BLK; }
        else                  { src = zt; base = (rb - ROWBLKS / 2) * ROWS_PER_BLK; }

        float4 acc = make_float4(0.f, 0.f, 0.f, 0.f);
        float ss = 0.f;
        #pragma unroll 4
        for (int r = 0; r < ROWS_PER_BLK; r++) {
            float4 v = src[(base + r) * D4 + t];
            acc.x += v.x; acc.y += v.y; acc.z += v.z; acc.w += v.w;
            ss += v.x * v.x + v.y * v.y + v.z * v.z + v.w * v.w;
        }
        g_colsum_part[rb * D4 + t] = acc;

        #pragma unroll
        for (int o = 16; o > 0; o >>= 1) ss += __shfl_down_sync(0xffffffffu, ss, o);
        __shared__ float sw[8];
        if ((t & 31) == 0) sw[t >> 5] = ss;
        __syncthreads();
        if (t == 0) {
            float sum = 0.f;
            #pragma unroll
            for (int w = 0; w < 8; w++) sum += sw[w];
            g_sumsq_part[rb] = sum;
        }
    } else {
        // ---- distance block: 4 pairwise sq-distances for index i ----
        const int i = bid - ROWBLKS;
        const int j = (i + 1) & (BN - 1);
        float4 a = zs[i * D4 + t];
        float4 b = zs[j * D4 + t];
        float4 c = zt[i * D4 + t];
        float4 e = zt[j * D4 + t];
        float v0 = sq4(a, b);   // |zs_i - zs_j|^2
        float v1 = sq4(c, e);   // |zt_i - zt_j|^2
        float v2 = sq4(a, e);   // |zs_i - zt_j|^2
        float v3 = sq4(b, c);   // |zs_j - zt_i|^2
        #pragma unroll
        for (int o = 16; o > 0; o >>= 1) {
            v0 += __shfl_down_sync(0xffffffffu, v0, o);
            v1 += __shfl_down_sync(0xffffffffu, v1, o);
            v2 += __shfl_down_sync(0xffffffffu, v2, o);
            v3 += __shfl_down_sync(0xffffffffu, v3, o);
        }
        __shared__ float s[8][4];
        if ((t & 31) == 0) {
            int w = t >> 5;
            s[w][0] = v0; s[w][1] = v1; s[w][2] = v2; s[w][3] = v3;
        }
        __syncthreads();
        if (t < 4) {
            float sum = 0.f;
            #pragma unroll
            for (int w = 0; w < 8; w++) sum += s[w][t];
            ((float*)g_dist4)[i * 4 + t] = sum;
        }
    }
}

// Warp-shuffle block reduction for 1024 threads (2 barriers, no tree loop).
__device__ __forceinline__ float block_reduce_1024(float v, float* red) {
    #pragma unroll
    for (int o = 16; o > 0; o >>= 1) v += __shfl_down_sync(0xffffffffu, v, o);
    if ((threadIdx.x & 31) == 0) red[threadIdx.x >> 5] = v;
    __syncthreads();
    if (threadIdx.x < 32) {
        v = red[threadIdx.x];
        #pragma unroll
        for (int o = 16; o > 0; o >>= 1) v += __shfl_down_sync(0xffffffffu, v, o);
        if (threadIdx.x == 0) red[0] = v;
    }
    __syncthreads();
    v = red[0];
    __syncthreads();   // protect red[] for the next reduction
    return v;
}

__global__ __launch_bounds__(1024)
void mk_finalize(float* __restrict__ out) {
    const int t = threadIdx.x;
    __shared__ float4 sm4[3 * D4];   // chunks 1..3 partial colsums (12 KB)
    __shared__ float red[32];
    __shared__ float coef[3];

    // ---- colsum partial reduce: all 1024 threads (4 chunks x 256 cols) ----
    const int col = t & (D4 - 1);
    const int chunk = t >> 8;                // 0..3, 16 partials each
    float4 s = make_float4(0.f, 0.f, 0.f, 0.f);
    #pragma unroll
    for (int p = 0; p < ROWBLKS / 4; p++) {
        float4 v = g_colsum_part[(chunk * (ROWBLKS / 4) + p) * D4 + col];
        s.x += v.x; s.y += v.y; s.z += v.z; s.w += v.w;
    }
    if (chunk > 0) sm4[(chunk - 1) * D4 + col] = s;
    __syncthreads();

    float my_sq = 0.f;
    if (chunk == 0) {
        #pragma unroll
        for (int c = 0; c < 3; c++) {
            float4 v = sm4[c * D4 + col];
            s.x += v.x; s.y += v.y; s.z += v.z; s.w += v.w;
        }
        my_sq = s.x * s.x + s.y * s.y + s.z * s.z + s.w * s.w;
    }
    float my_ss = (t < ROWBLKS) ? g_sumsq_part[t] : 0.f;

    float S2 = block_reduce_1024(my_sq, red);
    float SS = block_reduce_1024(my_ss, red);

    if (t == 0) {
        const double N = 2.0 * (double)BN;
        double mean_d2 = (2.0 * N * (double)SS - 2.0 * (double)S2) / (N * N);
        const double alphas[3] = {0.5, 1.0, 2.0};
        #pragma unroll
        for (int a = 0; a < 3; a++)
            coef[a] = (float)(-1.0 / (2.0 * alphas[a] * mean_d2));
    }
    __syncthreads();

    // ---- kernel evaluations + signed sum (fast exp) ----
    float local = 0.f;
    #pragma unroll
    for (int k = 0; k < BN / 1024; k++) {
        float4 d = g_dist4[k * 1024 + t];
        #pragma unroll
        for (int a = 0; a < 3; a++) {
            float c = coef[a];
            local += __expf(c * d.x) + __expf(c * d.y)
                   - __expf(c * d.z) - __expf(c * d.w);
        }
    }
    float tot = block_reduce_1024(local, red);
    if (t == 0) out[0] = tot / (float)BN;
}

extern "C" void kernel_launch(void* const* d_in, const int* in_sizes, int n_in,
                              void* d_out, int out_size) {
    const float4* zs = (const float4*)d_in[0];
    const float4* zt = (const float4*)d_in[1];
    mk_main_pass<<<BN + ROWBLKS, 256>>>(zs, zt);
    mk_finalize<<<1, 1024>>>((float*)d_out);
}